// round 4
// baseline (speedup 1.0000x reference)
#include <cuda_runtime.h>
#include <stdint.h>

#define NB 64
#define NS 512
#define ND 768
#define NROWS (NB * NS)            // 32768
#define F4_PER_ROW (ND / 4)        // 192
#define TOTAL_F4 (NROWS * F4_PER_ROW)  // 6,291,456

__device__ float g_scale[NROWS];   // 128 KB scratch, L2-resident

__device__ __forceinline__ uint32_t rotl32(uint32_t x, int r) {
    return (x << r) | (x >> (32 - r));
}

// JAX threefry2x32-20, key = (0, 42), partitionable path:
//   counter for element i is (hi, lo) = (0, i); 32-bit output = lane0 ^ lane1
__device__ __forceinline__ uint32_t jax_threefry_bits_partitionable(uint32_t i) {
    const uint32_t ks0 = 0u;
    const uint32_t ks1 = 42u;
    const uint32_t ks2 = 0u ^ 42u ^ 0x1BD11BDAu;

    uint32_t x0 = 0u + ks0;   // counts_hi = 0
    uint32_t x1 = i + ks1;    // counts_lo = i

#define TF_R4(r0, r1, r2, r3)                                   \
    x0 += x1; x1 = rotl32(x1, r0); x1 ^= x0;                    \
    x0 += x1; x1 = rotl32(x1, r1); x1 ^= x0;                    \
    x0 += x1; x1 = rotl32(x1, r2); x1 ^= x0;                    \
    x0 += x1; x1 = rotl32(x1, r3); x1 ^= x0;

    TF_R4(13, 15, 26, 6);  x0 += ks1; x1 += ks2 + 1u;
    TF_R4(17, 29, 16, 24); x0 += ks2; x1 += ks0 + 2u;
    TF_R4(13, 15, 26, 6);  x0 += ks0; x1 += ks1 + 3u;
    TF_R4(17, 29, 16, 24); x0 += ks1; x1 += ks2 + 4u;
    TF_R4(13, 15, 26, 6);  x0 += ks2; x1 += ks0 + 5u;
#undef TF_R4

    return x0 ^ x1;
}

// ── Kernel A: one thread per (b, j) row → scale ─────────────────────────────
__global__ __launch_bounds__(256)
void scale_kernel(const int* __restrict__ abi,   // [B,2]
                  const int* __restrict__ tlen,  // [B]
                  const int* __restrict__ alen)  // [B]
{
    const int row = blockIdx.x * 256 + threadIdx.x;   // [0, NROWS)
    const int b = row >> 9;                 // row / NS
    const int j = row & (NS - 1);           // row % NS

    const int2 bb = *(const int2*)(abi + 2 * b);
    const int tli = tlen[b];
    const float jf  = (float)j;
    const float b0f = (float)bb.x;
    const float b1f = (float)bb.y;
    const float tlf = (float)tli;
    const float ctx = (float)(tli - alen[b]);

    // Exact IEEE divisions so fast-math can't shift the comparison boundary.
    float prox;
    if (jf < b0f)       prox = 1.0f - __fdiv_rn(b0f - jf, ctx);
    else if (jf <= b1f) prox = __fdiv_rn(1.0f, ctx);
    else                prox = 1.0f - __fdiv_rn(jf - b1f, ctx);
    if (!(jf < tlf)) prox = 0.0f;
    prox = fminf(fmaxf(prox, 0.0f), 1.0f);

    const uint32_t bits = jax_threefry_bits_partitionable((uint32_t)row);
    const float u = __uint_as_float((bits >> 9) | 0x3f800000u) - 1.0f;
    const float mask = (u < prox) ? 1.0f : 0.0f;

    g_scale[row] = __fdiv_rn(mask, prox + 1e-5f);
}

// ── Kernel B: pure stream  out = scale[row] * x ─────────────────────────────
// 4 float4 per thread, front-batched loads, streaming stores.
__global__ __launch_bounds__(256)
void stream_kernel(const float4* __restrict__ x,
                   float4* __restrict__ out) {
    const int base = blockIdx.x * 1024 + threadIdx.x;   // float4 index

    float4 v[4];
    float sc[4];
#pragma unroll
    for (int k = 0; k < 4; k++) {
        const int idx = base + k * 256;
        v[k] = x[idx];
        sc[k] = g_scale[idx / F4_PER_ROW];   // mul-shift div; mostly L1 hits
    }

#pragma unroll
    for (int k = 0; k < 4; k++) {
        float4 w = v[k];
        const float s = sc[k];
        w.x *= s; w.y *= s; w.z *= s; w.w *= s;
        // Streaming store: out is never re-read — keep it from evicting x in L2.
        __stcs(&out[base + k * 256], w);
    }
}

extern "C" void kernel_launch(void* const* d_in, const int* in_sizes, int n_in,
                              void* d_out, int out_size) {
    const float4* x = (const float4*)d_in[0];
    const int* abi  = (const int*)d_in[1];
    const int* tlen = (const int*)d_in[2];
    const int* alen = (const int*)d_in[3];
    float4* out = (float4*)d_out;

    scale_kernel<<<NROWS / 256, 256>>>(abi, tlen, alen);        // 128 blocks
    stream_kernel<<<TOTAL_F4 / 1024, 256>>>(x, out);            // 6144 blocks
}

// round 5
// speedup vs baseline: 1.0494x; 1.0494x over previous
#include <cuda_runtime.h>
#include <stdint.h>

#define NB 64
#define NS 512
#define ND 768
#define NROWS (NB * NS)          // 32768
#define F4_PER_ROW (ND / 4)      // 192
#define ROWS_PER_BLOCK 8         // one row per warp
#define THREADS 256
#define F4_PER_LANE 6            // 192 / 32

__device__ __forceinline__ uint32_t rotl32(uint32_t x, int r) {
    return (x << r) | (x >> (32 - r));
}

// JAX threefry2x32-20, key = (0, 42), partitionable path:
//   counter for element i is (hi, lo) = (0, i); 32-bit output = lane0 ^ lane1
__device__ __forceinline__ uint32_t jax_threefry_bits_partitionable(uint32_t i) {
    const uint32_t ks0 = 0u;
    const uint32_t ks1 = 42u;
    const uint32_t ks2 = 0u ^ 42u ^ 0x1BD11BDAu;

    uint32_t x0 = 0u + ks0;   // counts_hi = 0
    uint32_t x1 = i + ks1;    // counts_lo = i

#define TF_R4(r0, r1, r2, r3)                                   \
    x0 += x1; x1 = rotl32(x1, r0); x1 ^= x0;                    \
    x0 += x1; x1 = rotl32(x1, r1); x1 ^= x0;                    \
    x0 += x1; x1 = rotl32(x1, r2); x1 ^= x0;                    \
    x0 += x1; x1 = rotl32(x1, r3); x1 ^= x0;

    TF_R4(13, 15, 26, 6);  x0 += ks1; x1 += ks2 + 1u;
    TF_R4(17, 29, 16, 24); x0 += ks2; x1 += ks0 + 2u;
    TF_R4(13, 15, 26, 6);  x0 += ks0; x1 += ks1 + 3u;
    TF_R4(17, 29, 16, 24); x0 += ks1; x1 += ks2 + 4u;
    TF_R4(13, 15, 26, 6);  x0 += ks2; x1 += ks0 + 5u;
#undef TF_R4

    return x0 ^ x1;
}

__global__ __launch_bounds__(THREADS)
void position_dropout_kernel(const float4* __restrict__ x,
                             const int* __restrict__ abi,   // [B,2]
                             const int* __restrict__ tlen,  // [B]
                             const int* __restrict__ alen,  // [B]
                             float4* __restrict__ out) {
    const uint32_t t = threadIdx.x;
    const uint32_t lane = t & 31u;
    const uint32_t row = blockIdx.x * ROWS_PER_BLOCK + (t >> 5);  // one row/warp
    const uint32_t base = row * F4_PER_ROW + lane;                // 32-bit index

    // Front-batch 6 independent float4 loads; the redundant per-lane RNG
    // chain below overlaps with these in-flight loads.
    float4 v[F4_PER_LANE];
#pragma unroll
    for (int k = 0; k < F4_PER_LANE; k++)
        v[k] = x[base + 32u * k];

    // All 32 lanes compute the identical scale — same issue cost as 1
    // predicated lane, but no shfl / branch envelope on the store path.
    const uint32_t b = row >> 9;                 // row / NS
    const uint32_t j = row & (NS - 1u);          // row % NS

    const int2 bb = *(const int2*)(abi + 2u * b);
    const int tli = tlen[b];
    const float jf  = (float)j;
    const float b0f = (float)bb.x;
    const float b1f = (float)bb.y;
    const float tlf = (float)tli;
    const float ctx = (float)(tli - alen[b]);

    // Exact IEEE divisions so fast-math can't shift the comparison boundary.
    float prox;
    if (jf < b0f)       prox = 1.0f - __fdiv_rn(b0f - jf, ctx);
    else if (jf <= b1f) prox = __fdiv_rn(1.0f, ctx);
    else                prox = 1.0f - __fdiv_rn(jf - b1f, ctx);
    if (!(jf < tlf)) prox = 0.0f;
    prox = fminf(fmaxf(prox, 0.0f), 1.0f);

    const uint32_t bits = jax_threefry_bits_partitionable(row);
    const float u = __uint_as_float((bits >> 9) | 0x3f800000u) - 1.0f;
    const float mask = (u < prox) ? 1.0f : 0.0f;

    const float sc = __fdiv_rn(mask, prox + 1e-5f);

#pragma unroll
    for (int k = 0; k < F4_PER_LANE; k++) {
        float4 w = v[k];
        w.x *= sc; w.y *= sc; w.z *= sc; w.w *= sc;
        out[base + 32u * k] = w;
    }
}

extern "C" void kernel_launch(void* const* d_in, const int* in_sizes, int n_in,
                              void* d_out, int out_size) {
    const float4* x = (const float4*)d_in[0];
    const int* abi  = (const int*)d_in[1];
    const int* tlen = (const int*)d_in[2];
    const int* alen = (const int*)d_in[3];
    float4* out = (float4*)d_out;

    const int nblocks = NROWS / ROWS_PER_BLOCK;          // 4096
    position_dropout_kernel<<<nblocks, THREADS>>>(x, abi, tlen, alen, out);
}